// round 6
// baseline (speedup 1.0000x reference)
#include <cuda_runtime.h>
#include <cuda_bf16.h>
#include <cstdint>

#define GG 256
#define NN 512
#define KK 6
#define FF 64
#define TT (GG*NN)

typedef unsigned long long u64;

// scratch (static device arrays: no allocation allowed)
__device__ int   g_idx[TT*KK];
__device__ float g_hA[TT*FF];
__device__ float g_hB[TT*FF];
__device__ float g_part[(TT/128)*FF];   // per-128-row-block pooled partials

// knn smem layout: [bf16 swizzled 512x64 = 64KB][fp32 rot-swizzled 512x64 = 128KB][sq 2KB]
#define KNN_BF_BYTES (NN*FF*2)
#define KNN_X_OFF    KNN_BF_BYTES
#define KNN_SQ_OFF   (KNN_BF_BYTES + NN*FF*4)
#define KNN_SMEM     (KNN_SQ_OFF + NN*4)

#define LIN12_SMEM ((128*64 + 2*64*64 + 256) * 4)
#define GCONV_SMEM ((128*64 + 64*64 + 64) * 4)
#define LIN34_SMEM ((128*64 + 2*64*64 + 16*64 + 256) * 4)

// ---------------------------------------------------------------------------
// packed f32x2 helpers
// ---------------------------------------------------------------------------
__device__ __forceinline__ u64 fma2(u64 a, u64 b, u64 c) {
    u64 d;
    asm("fma.rn.f32x2 %0, %1, %2, %3;" : "=l"(d) : "l"(a), "l"(b), "l"(c));
    return d;
}
__device__ __forceinline__ u64 pack2(float lo, float hi) {
    u64 d;
    asm("mov.b64 %0, {%1, %2};" : "=l"(d) : "f"(lo), "f"(hi));
    return d;
}
__device__ __forceinline__ float2 unpack2(u64 v) {
    float lo, hi;
    asm("mov.b64 {%0, %1}, %2;" : "=f"(lo), "=f"(hi) : "l"(v));
    return make_float2(lo, hi);
}

// ---------------------------------------------------------------------------
// bf16 mma.sync m16n8k16 (classic tensor path; sm_80+ PTX, no arch suffix)
// ---------------------------------------------------------------------------
__device__ __forceinline__ void mma_bf16(float d[4],
    uint32_t a0, uint32_t a1, uint32_t a2, uint32_t a3,
    uint32_t b0, uint32_t b1)
{
    asm volatile(
        "mma.sync.aligned.m16n8k16.row.col.f32.bf16.bf16.f32 "
        "{%0,%1,%2,%3}, {%4,%5,%6,%7}, {%8,%9}, {%0,%1,%2,%3};"
        : "+f"(d[0]), "+f"(d[1]), "+f"(d[2]), "+f"(d[3])
        : "r"(a0), "r"(a1), "r"(a2), "r"(a3), "r"(b0), "r"(b1));
}

// bf16 swizzle: feature k of node n stored at k' = (k + 8*(n&7)) & 63 (k even pairs stay adjacent)
__device__ __forceinline__ int brot(int n, int k) { return (k + 8 * (n & 7)) & 63; }

// ===========================================================================
// kNN via bf16 mma.sync. grid = GG*2 blocks x 256 thr (8 warps).
// Block b: graph g = b>>1, query rows half = (b&1)*256; warp w owns 32 rows.
// Approx D = Xq.Xc^T (bf16, f32 accum). Per-LANE top-8 over disjoint 128-cand
// subset -> per-lane fp32-exact refine of its 8 -> lex (d,idx) merge -> top-6.
// ===========================================================================
__global__ void __launch_bounds__(256, 1) knn_bf16_kernel(const float* __restrict__ x)
{
    extern __shared__ char smraw[];
    __nv_bfloat16* bf = (__nv_bfloat16*)smraw;          // swizzled bf16 graph
    float*  xs  = (float*)(smraw + KNN_X_OFF);          // rot-swizzled fp32 graph
    float*  sq  = (float*)(smraw + KNN_SQ_OFF);
    float4* xs4 = (float4*)xs;

    const int g    = blockIdx.x >> 1;
    const int half = (blockIdx.x & 1) * 256;
    const int tid  = threadIdx.x;
    const int warp = tid >> 5;
    const int lane = tid & 31;
    const int gID  = lane >> 2;
    const int tq   = lane & 3;
    const float* xg = x + (size_t)g * NN * FF;
    const float4* xg4 = (const float4*)xg;

    // fill: fp32 rot-swizzled + bf16 rot-swizzled
    for (int i = tid; i < NN * FF / 4; i += 256) {
        const int n  = i >> 4;
        const int i4 = i & 15;
        const float4 v = xg4[i];
        xs4[n * 16 + ((i4 + (n & 15)) & 15)] = v;
        // bf16: 4 consecutive k at k4 = i4*4, rotated (stays 8B-aligned contiguous)
        const int kr = brot(n, i4 * 4);
        __nv_bfloat162 p0 = __floats2bfloat162_rn(v.x, v.y);
        __nv_bfloat162 p1 = __floats2bfloat162_rn(v.z, v.w);
        uint2 pp;
        pp.x = *(uint32_t*)&p0;
        pp.y = *(uint32_t*)&p1;
        *(uint2*)((char*)bf + n * 128 + kr * 2) = pp;
    }
    // fp32 norms from global (2 rows per thread)
    #pragma unroll
    for (int rr = 0; rr < 2; rr++) {
        const int r = tid + rr * 256;
        const float4* row = xg4 + r * 16;
        float s0 = 0.f, s1 = 0.f;
        #pragma unroll
        for (int k = 0; k < 16; k += 2) {
            float4 a = row[k], b = row[k+1];
            s0 = fmaf(a.x, a.x, s0); s0 = fmaf(a.y, a.y, s0);
            s0 = fmaf(a.z, a.z, s0); s0 = fmaf(a.w, a.w, s0);
            s1 = fmaf(b.x, b.x, s1); s1 = fmaf(b.y, b.y, s1);
            s1 = fmaf(b.z, b.z, s1); s1 = fmaf(b.w, b.w, s1);
        }
        sq[r] = s0 + s1;
    }
    __syncthreads();

    // query rows for this thread
    const int q0 = half + warp * 32;
    int qrow[4];
    qrow[0] = q0 + gID;      qrow[1] = q0 + 8 + gID;
    qrow[2] = q0 + 16 + gID; qrow[3] = q0 + 24 + gID;

    // preload A fragments: 2 row-tiles x 4 k-steps x 4 regs (bf16x2 each)
    uint32_t Af[2][4][4];
    #pragma unroll
    for (int kk = 0; kk < 4; kk++) {
        const int k0 = kk * 16;
        #pragma unroll
        for (int tile = 0; tile < 2; tile++) {
            const int ra = qrow[tile * 2];
            const int rb = qrow[tile * 2 + 1];
            Af[tile][kk][0] = *(const uint32_t*)((char*)bf + ra*128 + brot(ra, k0 + 2*tq) * 2);
            Af[tile][kk][1] = *(const uint32_t*)((char*)bf + rb*128 + brot(rb, k0 + 2*tq) * 2);
            Af[tile][kk][2] = *(const uint32_t*)((char*)bf + ra*128 + brot(ra, k0 + 2*tq + 8) * 2);
            Af[tile][kk][3] = *(const uint32_t*)((char*)bf + rb*128 + brot(rb, k0 + 2*tq + 8) * 2);
        }
    }

    // per-row, per-lane top-8 trackers over this lane's candidate subset
    float sd[4][8]; int si[4][8];
    float wv[4]; int ws[4];
    #pragma unroll
    for (int r = 0; r < 4; r++) {
        #pragma unroll
        for (int s = 0; s < 8; s++) { sd[r][s] = 3.0e38f; si[r][s] = 0; }
        wv[r] = 3.0e38f; ws[r] = 0;
    }

    #pragma unroll 1
    for (int ct = 0; ct < 64; ct++) {
        const int cand0 = ct * 8;
        const int nb = cand0 + gID;
        float acc0[4] = {0.f, 0.f, 0.f, 0.f};
        float acc1[4] = {0.f, 0.f, 0.f, 0.f};
        #pragma unroll
        for (int kk = 0; kk < 4; kk++) {
            const int k0 = kk * 16;
            const uint32_t b0 = *(const uint32_t*)((char*)bf + nb*128 + brot(nb, k0 + 2*tq) * 2);
            const uint32_t b1 = *(const uint32_t*)((char*)bf + nb*128 + brot(nb, k0 + 2*tq + 8) * 2);
            mma_bf16(acc0, Af[0][kk][0], Af[0][kk][1], Af[0][kk][2], Af[0][kk][3], b0, b1);
            mma_bf16(acc1, Af[1][kk][0], Af[1][kk][1], Af[1][kk][2], Af[1][kk][3], b0, b1);
        }
        const int c0 = cand0 + 2 * tq;
        const int c1 = c0 + 1;
        const float sq_c0 = sq[c0], sq_c1 = sq[c1];
        // key = sq[c] - 2*dot (sq[q] constant per row; ranking unchanged)
        const float key[4][2] = {
            { sq_c0 - 2.f*acc0[0], sq_c1 - 2.f*acc0[1] },
            { sq_c0 - 2.f*acc0[2], sq_c1 - 2.f*acc0[3] },
            { sq_c0 - 2.f*acc1[0], sq_c1 - 2.f*acc1[1] },
            { sq_c0 - 2.f*acc1[2], sq_c1 - 2.f*acc1[3] } };
        #pragma unroll
        for (int r = 0; r < 4; r++) {
            #pragma unroll
            for (int cc = 0; cc < 2; cc++) {
                const int j = cc ? c1 : c0;
                const float d = key[r][cc];
                if (j != qrow[r] && d < wv[r]) {
                    sd[r][ws[r]] = d; si[r][ws[r]] = j;
                    wv[r] = sd[r][0]; ws[r] = 0;
                    #pragma unroll
                    for (int s = 1; s < 8; s++)
                        if (sd[r][s] > wv[r]) { wv[r] = sd[r][s]; ws[r] = s; }
                }
            }
        }
    }

    // per-lane fp32-exact refine of its own 8 candidates (overwrite sd with exact d)
    #pragma unroll 1
    for (int r = 0; r < 4; r++) {
        const int q = qrow[r];
        const float sqq = sq[q];
        float4 qv[16];
        #pragma unroll
        for (int i4 = 0; i4 < 16; i4++)
            qv[i4] = xs4[q * 16 + ((i4 + (q & 15)) & 15)];
        #pragma unroll
        for (int s = 0; s < 8; s++) {
            const int c = si[r][s];
            float a0 = 0.f, a1 = 0.f;
            #pragma unroll
            for (int i4 = 0; i4 < 16; i4 += 2) {
                const float4 v0 = xs4[c * 16 + ((i4     + (c & 15)) & 15)];
                const float4 v1 = xs4[c * 16 + ((i4 + 1 + (c & 15)) & 15)];
                a0 = fmaf(qv[i4].x,   v0.x, a0); a0 = fmaf(qv[i4].y,   v0.y, a0);
                a0 = fmaf(qv[i4].z,   v0.z, a0); a0 = fmaf(qv[i4].w,   v0.w, a0);
                a1 = fmaf(qv[i4+1].x, v1.x, a1); a1 = fmaf(qv[i4+1].y, v1.y, a1);
                a1 = fmaf(qv[i4+1].z, v1.z, a1); a1 = fmaf(qv[i4+1].w, v1.w, a1);
            }
            const float dot = a0 + a1;
            sd[r][s] = __fsub_rn(sqq + sq[c], __fmul_rn(2.f, dot));
        }
    }

    // merge the 4 lanes' exact (d, idx) pairs per row; lexicographic top-6
    const int base = g * NN;
    #pragma unroll 1
    for (int r = 0; r < 4; r++) {
        float b6d[6]; int b6i[6];
        float wd = 3.0e38f; int wi = 0x7fffffff; int wslot = 0;
        #pragma unroll
        for (int t = 0; t < 6; t++) { b6d[t] = 3.0e38f; b6i[t] = 0x7fffffff; }

        #pragma unroll
        for (int st = 0; st < 4; st++) {
            #pragma unroll
            for (int s = 0; s < 8; s++) {
                const float d = __shfl_sync(0xffffffffu, sd[r][s], (gID << 2) + st);
                const int   i = __shfl_sync(0xffffffffu, si[r][s], (gID << 2) + st);
                if (tq == 0) {
                    const bool better = (d < wd) || (d == wd && i < wi);
                    if (better) {
                        b6d[wslot] = d; b6i[wslot] = i;
                        wd = b6d[0]; wi = b6i[0]; wslot = 0;
                        #pragma unroll
                        for (int t = 1; t < 6; t++)
                            if (b6d[t] > wd || (b6d[t] == wd && b6i[t] > wi)) {
                                wd = b6d[t]; wi = b6i[t]; wslot = t;
                            }
                    }
                }
            }
        }
        if (tq == 0) {
            #pragma unroll
            for (int t = 0; t < 6; t++)
                g_idx[(size_t)(base + qrow[r]) * KK + t] = base + b6i[t];
        }
    }
}

// ---------------------------------------------------------------------------
// 128-row x 64-col tile matmul from smem, FFMA2 over column pairs.
// ---------------------------------------------------------------------------
__device__ __forceinline__ void mm_tile2(const float* __restrict__ xs,
                                         const float* __restrict__ Ws,
                                         u64 acc2[8][2], int rg, int cg)
{
    #pragma unroll
    for (int r = 0; r < 8; r++) { acc2[r][0] = 0ull; acc2[r][1] = 0ull; }
    #pragma unroll 2
    for (int k = 0; k < 64; k += 4) {
        const ulonglong2 w0 = *(const ulonglong2*)&Ws[(k+0)*64 + cg];
        const ulonglong2 w1 = *(const ulonglong2*)&Ws[(k+1)*64 + cg];
        const ulonglong2 w2 = *(const ulonglong2*)&Ws[(k+2)*64 + cg];
        const ulonglong2 w3 = *(const ulonglong2*)&Ws[(k+3)*64 + cg];
        #pragma unroll
        for (int r = 0; r < 8; r++) {
            const float4 xv = *(const float4*)&xs[(rg*8 + r)*64 + k];
            const u64 x0 = pack2(xv.x, xv.x);
            const u64 x1 = pack2(xv.y, xv.y);
            const u64 x2 = pack2(xv.z, xv.z);
            const u64 x3 = pack2(xv.w, xv.w);
            acc2[r][0] = fma2(x0, w0.x, acc2[r][0]);
            acc2[r][1] = fma2(x0, w0.y, acc2[r][1]);
            acc2[r][0] = fma2(x1, w1.x, acc2[r][0]);
            acc2[r][1] = fma2(x1, w1.y, acc2[r][1]);
            acc2[r][0] = fma2(x2, w2.x, acc2[r][0]);
            acc2[r][1] = fma2(x2, w2.y, acc2[r][1]);
            acc2[r][0] = fma2(x3, w3.x, acc2[r][0]);
            acc2[r][1] = fma2(x3, w3.y, acc2[r][1]);
        }
    }
}

// ---------------------------------------------------------------------------
// Fused prelu(x@W1+b1) -> prelu(.@W2+b2). 1024 blocks x 256 thr, 128 rows/block.
// ---------------------------------------------------------------------------
__global__ void __launch_bounds__(256) lin12_kernel(
    const float* __restrict__ x,
    const float* __restrict__ W1, const float* __restrict__ b1, const float* __restrict__ a1,
    const float* __restrict__ W2, const float* __restrict__ b2, const float* __restrict__ a2,
    float* __restrict__ out)
{
    extern __shared__ float smf[];
    float* xs = smf;             // 8192
    float* Ws = smf + 8192;      // 8192 (W1 | W2)
    float* bs = smf + 16384;     // 256 (b1,a1,b2,a2)
    const int tid = threadIdx.x;
    const size_t rowbase = (size_t)blockIdx.x * 128;

    float4* xs4 = (float4*)xs;
    const float4* xin = (const float4*)(x + rowbase * FF);
    for (int i = tid; i < 2048; i += 256) xs4[i] = xin[i];
    float4* Ws4 = (float4*)Ws;
    for (int i = tid; i < 1024; i += 256) {
        Ws4[i]        = ((const float4*)W1)[i];
        Ws4[1024 + i] = ((const float4*)W2)[i];
    }
    if (tid < 64) { bs[tid] = b1[tid]; bs[64+tid] = a1[tid]; bs[128+tid] = b2[tid]; bs[192+tid] = a2[tid]; }
    __syncthreads();

    const int rg = tid >> 4, cg = (tid & 15) * 4;
    u64 acc2[8][2];
    mm_tile2(xs, Ws, acc2, rg, cg);
    __syncthreads();
    #pragma unroll
    for (int r = 0; r < 8; r++) {
        const float2 p0 = unpack2(acc2[r][0]);
        const float2 p1 = unpack2(acc2[r][1]);
        const float a4[4] = {p0.x, p0.y, p1.x, p1.y};
        #pragma unroll
        for (int c = 0; c < 4; c++) {
            float v = a4[c] + bs[cg + c];
            v = (v >= 0.f) ? v : v * bs[64 + cg + c];
            xs[(rg*8 + r)*64 + cg + c] = v;
        }
    }
    __syncthreads();
    mm_tile2(xs, Ws + 4096, acc2, rg, cg);
    #pragma unroll
    for (int r = 0; r < 8; r++) {
        const float2 p0 = unpack2(acc2[r][0]);
        const float2 p1 = unpack2(acc2[r][1]);
        float4 o;
        float v;
        v = p0.x + bs[128+cg+0]; o.x = (v >= 0.f) ? v : v * bs[192+cg+0];
        v = p0.y + bs[128+cg+1]; o.y = (v >= 0.f) ? v : v * bs[192+cg+1];
        v = p1.x + bs[128+cg+2]; o.z = (v >= 0.f) ? v : v * bs[192+cg+2];
        v = p1.y + bs[128+cg+3]; o.w = (v >= 0.f) ? v : v * bs[192+cg+3];
        *(float4*)&out[(rowbase + rg*8 + r)*FF + cg] = o;
    }
}

// ---------------------------------------------------------------------------
// GeneralConv: out[i] = (sum_{j in nbr(i)} h[j]) @ W + 6*b + h[i]
// ---------------------------------------------------------------------------
__global__ void __launch_bounds__(256) gconv_kernel(
    const float* __restrict__ hin,
    const float* __restrict__ Wc, const float* __restrict__ bc,
    float* __restrict__ out)
{
    extern __shared__ float smf[];
    float* ss = smf;             // 8192 (gathered neighbor sums)
    float* Ws = smf + 8192;      // 4096
    float* bs = smf + 12288;     // 64
    const int tid = threadIdx.x;
    const size_t rowbase = (size_t)blockIdx.x * 128;

    float4* Ws4 = (float4*)Ws;
    for (int i = tid; i < 1024; i += 256) Ws4[i] = ((const float4*)Wc)[i];
    if (tid < 64) bs[tid] = bc[tid];

    {   // gather-sum: 2 threads per row (32 feats each)
        const int r = tid >> 1;
        const int half = (tid & 1) * 8;     // float4 chunk offset
        const int* ip = g_idx + ((size_t)rowbase + r) * KK;
        float4 acc4[8];
        #pragma unroll
        for (int c = 0; c < 8; c++) acc4[c] = make_float4(0.f, 0.f, 0.f, 0.f);
        #pragma unroll
        for (int j = 0; j < KK; j++) {
            const float4* nb = (const float4*)(hin + (size_t)ip[j] * FF) + half;
            #pragma unroll
            for (int c = 0; c < 8; c++) {
                float4 v = nb[c];
                acc4[c].x += v.x; acc4[c].y += v.y; acc4[c].z += v.z; acc4[c].w += v.w;
            }
        }
        float4* ss4 = (float4*)ss;
        #pragma unroll
        for (int c = 0; c < 8; c++) ss4[r*16 + half + c] = acc4[c];
    }
    __syncthreads();

    const int rg = tid >> 4, cg = (tid & 15) * 4;
    u64 acc2[8][2];
    mm_tile2(ss, Ws, acc2, rg, cg);
    #pragma unroll
    for (int r = 0; r < 8; r++) {
        const size_t row = rowbase + rg*8 + r;
        const float4 hv = *(const float4*)&hin[row*FF + cg];
        const float2 p0 = unpack2(acc2[r][0]);
        const float2 p1 = unpack2(acc2[r][1]);
        float4 o;
        o.x = p0.x + 6.f*bs[cg+0] + hv.x;
        o.y = p0.y + 6.f*bs[cg+1] + hv.y;
        o.z = p1.x + 6.f*bs[cg+2] + hv.z;
        o.w = p1.y + 6.f*bs[cg+3] + hv.w;
        *(float4*)&out[row*FF + cg] = o;
    }
}

// ---------------------------------------------------------------------------
// Fused prelu(.@W3+b3) -> prelu(.@W4+b4) -> per-block column partial sums (pool)
// ---------------------------------------------------------------------------
__global__ void __launch_bounds__(256) lin34_pool_kernel(
    const float* __restrict__ hin,
    const float* __restrict__ W3, const float* __restrict__ b3, const float* __restrict__ a3,
    const float* __restrict__ W4, const float* __restrict__ b4, const float* __restrict__ a4)
{
    extern __shared__ float smf[];
    float* xs = smf;             // 8192
    float* Ws = smf + 8192;      // 8192
    float* ps = smf + 16384;     // 1024
    float* bs = smf + 17408;     // 256
    const int tid = threadIdx.x;
    const size_t rowbase = (size_t)blockIdx.x * 128;

    float4* xs4 = (float4*)xs;
    const float4* xin = (const float4*)(hin + rowbase * FF);
    for (int i = tid; i < 2048; i += 256) xs4[i] = xin[i];
    float4* Ws4 = (float4*)Ws;
    for (int i = tid; i < 1024; i += 256) {
        Ws4[i]        = ((const float4*)W3)[i];
        Ws4[1024 + i] = ((const float4*)W4)[i];
    }
    if (tid < 64) { bs[tid] = b3[tid]; bs[64+tid] = a3[tid]; bs[128+tid] = b4[tid]; bs[192+tid] = a4[tid]; }
    __syncthreads();

    const int rg = tid >> 4, cg = (tid & 15) * 4;
    u64 acc2[8][2];
    mm_tile2(xs, Ws, acc2, rg, cg);
    __syncthreads();
    #pragma unroll
    for (int r = 0; r < 8; r++) {
        const float2 p0 = unpack2(acc2[r][0]);
        const float2 p1 = unpack2(acc2[r][1]);
        const float a4[4] = {p0.x, p0.y, p1.x, p1.y};
        #pragma unroll
        for (int c = 0; c < 4; c++) {
            float v = a4[c] + bs[cg + c];
            v = (v >= 0.f) ? v : v * bs[64 + cg + c];
            xs[(rg*8 + r)*64 + cg + c] = v;
        }
    }
    __syncthreads();
    mm_tile2(xs, Ws + 4096, acc2, rg, cg);

    float cs[4] = {0.f, 0.f, 0.f, 0.f};
    #pragma unroll
    for (int r = 0; r < 8; r++) {
        const float2 p0 = unpack2(acc2[r][0]);
        const float2 p1 = unpack2(acc2[r][1]);
        const float a4[4] = {p0.x, p0.y, p1.x, p1.y};
        #pragma unroll
        for (int c = 0; c < 4; c++) {
            float v = a4[c] + bs[128 + cg + c];
            v = (v >= 0.f) ? v : v * bs[192 + cg + c];
            cs[c] += v;
        }
    }
    #pragma unroll
    for (int c = 0; c < 4; c++) ps[rg*64 + cg + c] = cs[c];
    __syncthreads();

    if (tid < 64) {
        float s = 0.f;
        #pragma unroll
        for (int i = 0; i < 16; i++) s += ps[i*64 + tid];
        g_part[(size_t)blockIdx.x * FF + tid] = s;
    }
}

// ---------------------------------------------------------------------------
// Head MLP: pooled[64] -> 256 -> 256 -> 64 -> 1 (leaky 0.2). One block per graph.
// ---------------------------------------------------------------------------
__global__ void __launch_bounds__(256) head_kernel(
    const float* __restrict__ Wh1, const float* __restrict__ bh1,
    const float* __restrict__ Wh2, const float* __restrict__ bh2,
    const float* __restrict__ Wh3, const float* __restrict__ bh3,
    const float* __restrict__ Wh4, const float* __restrict__ bh4,
    float* __restrict__ out)
{
    __shared__ float p[64], y1[256], y2[256], y3[64];
    const int g = blockIdx.x, t = threadIdx.x;
    if (t < 64) {
        p[t] = g_part[(size_t)(g*4 + 0)*FF + t] + g_part[(size_t)(g*4 + 1)*FF + t]
             + g_part[(size_t)(g*4 + 2)*FF + t] + g_part[(size_t)(g*4 + 3)*FF + t];
    }
    __syncthreads();
    {
        float v = bh1[t];
        #pragma unroll 4
        for (int k = 0; k < 64; k++) v = fmaf(p[k], Wh1[k*256 + t], v);
        y1[t] = (v >= 0.f) ? v : 0.2f * v;
    }
    __syncthreads();
    {
        float v = bh2[t];
        #pragma unroll 4
        for (int k = 0; k < 256; k++) v = fmaf(y1[k], Wh2[k*256 + t], v);
        y2[t] = (v >= 0.f) ? v : 0.2f * v;
    }
    __syncthreads();
    if (t < 64) {
        float v = bh3[t];
        #pragma unroll 4
        for (int k = 0; k < 256; k++) v = fmaf(y2[k], Wh3[k*64 + t], v);
        y3[t] = (v >= 0.f) ? v : 0.2f * v;
    }
    __syncthreads();
    if (t == 0) {
        float v = bh4[0];
        #pragma unroll
        for (int k = 0; k < 64; k++) v = fmaf(y3[k], Wh4[k], v);
        out[g] = v;
    }
}

// ---------------------------------------------------------------------------
extern "C" void kernel_launch(void* const* d_in, const int* in_sizes, int n_in,
                              void* d_out, int out_size)
{
    const float* x   = (const float*)d_in[0];
    const float* W1  = (const float*)d_in[1];
    const float* b1  = (const float*)d_in[2];
    const float* a1  = (const float*)d_in[3];
    const float* W2  = (const float*)d_in[4];
    const float* b2  = (const float*)d_in[5];
    const float* a2  = (const float*)d_in[6];
    const float* Wc1 = (const float*)d_in[7];
    const float* bc1 = (const float*)d_in[8];
    const float* Wc2 = (const float*)d_in[9];
    const float* bc2 = (const float*)d_in[10];
    const float* Wc3 = (const float*)d_in[11];
    const float* bc3 = (const float*)d_in[12];
    const float* Wc4 = (const float*)d_in[13];
    const float* bc4 = (const float*)d_in[14];
    const float* W3  = (const float*)d_in[15];
    const float* b3  = (const float*)d_in[16];
    const float* a3  = (const float*)d_in[17];
    const float* W4  = (const float*)d_in[18];
    const float* b4  = (const float*)d_in[19];
    const float* a4  = (const float*)d_in[20];
    const float* Wh1 = (const float*)d_in[21];
    const float* bh1 = (const float*)d_in[22];
    const float* Wh2 = (const float*)d_in[23];
    const float* bh2 = (const float*)d_in[24];
    const float* Wh3 = (const float*)d_in[25];
    const float* bh3 = (const float*)d_in[26];
    const float* Wh4 = (const float*)d_in[27];
    const float* bh4 = (const float*)d_in[28];
    float* out = (float*)d_out;

    float *hA = nullptr, *hB = nullptr;
    cudaGetSymbolAddress((void**)&hA, g_hA);
    cudaGetSymbolAddress((void**)&hB, g_hB);

    cudaFuncSetAttribute(knn_bf16_kernel,  cudaFuncAttributeMaxDynamicSharedMemorySize, KNN_SMEM);
    cudaFuncSetAttribute(lin12_kernel,     cudaFuncAttributeMaxDynamicSharedMemorySize, LIN12_SMEM);
    cudaFuncSetAttribute(gconv_kernel,     cudaFuncAttributeMaxDynamicSharedMemorySize, GCONV_SMEM);
    cudaFuncSetAttribute(lin34_pool_kernel,cudaFuncAttributeMaxDynamicSharedMemorySize, LIN34_SMEM);

    knn_bf16_kernel<<<GG * 2, 256, KNN_SMEM>>>(x);
    lin12_kernel<<<TT/128, 256, LIN12_SMEM>>>(x, W1, b1, a1, W2, b2, a2, hA);
    gconv_kernel<<<TT/128, 256, GCONV_SMEM>>>(hA, Wc1, bc1, hB);
    gconv_kernel<<<TT/128, 256, GCONV_SMEM>>>(hB, Wc2, bc2, hA);
    gconv_kernel<<<TT/128, 256, GCONV_SMEM>>>(hA, Wc3, bc3, hB);
    gconv_kernel<<<TT/128, 256, GCONV_SMEM>>>(hB, Wc4, bc4, hA);
    lin34_pool_kernel<<<TT/128, 256, LIN34_SMEM>>>(hA, W3, b3, a3, W4, b4, a4);
    head_kernel<<<GG, 256>>>(Wh1, bh1, Wh2, bh2, Wh3, bh3, Wh4, bh4, out);
}

// round 8
// speedup vs baseline: 1.4469x; 1.4469x over previous
#include <cuda_runtime.h>
#include <cstdint>

#define GG 256
#define NN 512
#define KK 6
#define FF 64
#define TT (GG*NN)

typedef unsigned long long u64;

// scratch (static device arrays: no allocation allowed)
__device__ int   g_idx[TT*KK];
__device__ float g_hA[TT*FF];
__device__ float g_hB[TT*FF];
__device__ float g_part[(TT/128)*FF];   // per-128-row-block pooled partials

#define KNN_SMEM   ((NN*FF + NN) * 4)
#define GCONV_SMEM ((128*64 + 64*64 + 64) * 4)
#define LIN12_SMEM ((128*64 + 2*64*64 + 256) * 4)
#define LIN34_SMEM ((128*64 + 2*64*64 + 16*64 + 256) * 4)

// row-group rotation: rows of row-group rg are column-rotated by 4*(rg&7)
#define ROTG(rg) (4 * ((rg) & 7))
#define ROTR(r)  (4 * (((r) >> 3) & 7))

// ---------------------------------------------------------------------------
// packed f32x2 helpers
// ---------------------------------------------------------------------------
__device__ __forceinline__ u64 fma2(u64 a, u64 b, u64 c) {
    u64 d;
    asm("fma.rn.f32x2 %0, %1, %2, %3;" : "=l"(d) : "l"(a), "l"(b), "l"(c));
    return d;
}
__device__ __forceinline__ u64 pack2(float lo, float hi) {
    u64 d;
    asm("mov.b64 %0, {%1, %2};" : "=l"(d) : "f"(lo), "f"(hi));
    return d;
}
__device__ __forceinline__ float2 unpack2(u64 v) {
    float lo, hi;
    asm("mov.b64 {%0, %1}, %2;" : "=f"(lo), "=f"(hi) : "l"(v));
    return make_float2(lo, hi);
}

// ---------------------------------------------------------------------------
// kNN (R4 version, near fp32 floor): one block per graph, whole graph in smem.
// ---------------------------------------------------------------------------
__global__ void __launch_bounds__(256, 1) knn_kernel(const float* __restrict__ x)
{
    extern __shared__ float sm[];
    float* xs = sm;              // 512*64
    float* sq = sm + NN*FF;      // 512
    const int g   = blockIdx.x;
    const int tid = threadIdx.x;
    float4* xs4 = (float4*)xs;
    const float4* xg4 = (const float4*)(x + (size_t)g * NN * FF);

    for (int i = tid; i < NN*FF/4; i += 256) xs4[i] = xg4[i];
    __syncthreads();

    for (int r = tid; r < NN; r += 256) {
        const float4* row = xs4 + r*16;
        float s = 0.f;
        #pragma unroll
        for (int k2 = 0; k2 < 16; k2++) {
            float4 v = row[k2];
            s += v.x*v.x + v.y*v.y + v.z*v.z + v.w*v.w;
        }
        sq[r] = s;
    }
    __syncthreads();

    const int q0 = tid, q1 = tid + 256;
    const u64* xsu = (const u64*)xs;
    u64 xq0[32], xq1[32];
    #pragma unroll
    for (int k = 0; k < 32; k++) { xq0[k] = xsu[q0*32 + k]; xq1[k] = xsu[q1*32 + k]; }
    const float sq0 = sq[q0], sq1 = sq[q1];

    float bd0[6], bd1[6];
    int   bi0[6], bi1[6];
    #pragma unroll
    for (int t = 0; t < 6; t++) { bd0[t] = 3.0e38f; bd1[t] = 3.0e38f; bi0[t] = 0; bi1[t] = 0; }
    float w0v = 3.0e38f, w1v = 3.0e38f;
    int   w0s = 0,       w1s = 0;

    for (int j = 0; j < NN; j++) {
        const ulonglong2* cj = (const ulonglong2*)(xs + j*FF);
        u64 a0 = 0ull, b0 = 0ull, a1 = 0ull, b1 = 0ull;
        #pragma unroll
        for (int k = 0; k < 16; k++) {
            const ulonglong2 c = cj[k];
            a0 = fma2(xq0[2*k],   c.x, a0);
            b0 = fma2(xq0[2*k+1], c.y, b0);
            a1 = fma2(xq1[2*k],   c.x, a1);
            b1 = fma2(xq1[2*k+1], c.y, b1);
        }
        float2 f0a = unpack2(a0), f0b = unpack2(b0);
        float2 f1a = unpack2(a1), f1b = unpack2(b1);
        const float dot0 = (f0a.x + f0a.y) + (f0b.x + f0b.y);
        const float dot1 = (f1a.x + f1a.y) + (f1b.x + f1b.y);
        const float sj = sq[j];
        const float d0 = __fsub_rn(sq0 + sj, __fmul_rn(2.f, dot0));
        const float d1 = __fsub_rn(sq1 + sj, __fmul_rn(2.f, dot1));

        if (j != q0 && d0 < w0v) {
            bd0[w0s] = d0; bi0[w0s] = j;
            w0v = bd0[0]; w0s = 0;
            #pragma unroll
            for (int t = 1; t < 6; t++) if (bd0[t] > w0v) { w0v = bd0[t]; w0s = t; }
        }
        if (j != q1 && d1 < w1v) {
            bd1[w1s] = d1; bi1[w1s] = j;
            w1v = bd1[0]; w1s = 0;
            #pragma unroll
            for (int t = 1; t < 6; t++) if (bd1[t] > w1v) { w1v = bd1[t]; w1s = t; }
        }
    }

    const int base = g * NN;
    #pragma unroll
    for (int t = 0; t < 6; t++) {
        g_idx[(size_t)(base + q0)*KK + t] = base + bi0[t];
        g_idx[(size_t)(base + q1)*KK + t] = base + bi1[t];
    }
}

// ---------------------------------------------------------------------------
// mm88: 128x64x64 tile GEMM, 128 threads, 8 rows x 8 cols per thread.
// xs is rotation-swizzled ([row][ (col+ROTR(row))&63 ]); Ws is plain [k][c].
// ---------------------------------------------------------------------------
__device__ __forceinline__ void mm88(const float* __restrict__ xs,
                                     const float* __restrict__ Ws,
                                     u64 acc[8][4], int rg, int cg8)
{
    #pragma unroll
    for (int r = 0; r < 8; r++)
        #pragma unroll
        for (int p = 0; p < 4; p++) acc[r][p] = 0ull;
    const int rot = ROTG(rg);
    #pragma unroll 1
    for (int k0 = 0; k0 < 64; k0 += 4) {
        u64 w0[4], w1[4], w2[4], w3[4];
        {
            const ulonglong2 a0 = *(const ulonglong2*)&Ws[(k0+0)*64 + cg8];
            const ulonglong2 b0 = *(const ulonglong2*)&Ws[(k0+0)*64 + cg8 + 4];
            w0[0]=a0.x; w0[1]=a0.y; w0[2]=b0.x; w0[3]=b0.y;
            const ulonglong2 a1 = *(const ulonglong2*)&Ws[(k0+1)*64 + cg8];
            const ulonglong2 b1 = *(const ulonglong2*)&Ws[(k0+1)*64 + cg8 + 4];
            w1[0]=a1.x; w1[1]=a1.y; w1[2]=b1.x; w1[3]=b1.y;
            const ulonglong2 a2 = *(const ulonglong2*)&Ws[(k0+2)*64 + cg8];
            const ulonglong2 b2 = *(const ulonglong2*)&Ws[(k0+2)*64 + cg8 + 4];
            w2[0]=a2.x; w2[1]=a2.y; w2[2]=b2.x; w2[3]=b2.y;
            const ulonglong2 a3 = *(const ulonglong2*)&Ws[(k0+3)*64 + cg8];
            const ulonglong2 b3 = *(const ulonglong2*)&Ws[(k0+3)*64 + cg8 + 4];
            w3[0]=a3.x; w3[1]=a3.y; w3[2]=b3.x; w3[3]=b3.y;
        }
        const int kc = (k0 + rot) & 63;
        #pragma unroll
        for (int r = 0; r < 8; r++) {
            const float4 xv = *(const float4*)&xs[(rg*8 + r)*64 + kc];
            const u64 x0 = pack2(xv.x, xv.x);
            const u64 x1 = pack2(xv.y, xv.y);
            const u64 x2 = pack2(xv.z, xv.z);
            const u64 x3 = pack2(xv.w, xv.w);
            #pragma unroll
            for (int p = 0; p < 4; p++) {
                acc[r][p] = fma2(x0, w0[p], acc[r][p]);
                acc[r][p] = fma2(x1, w1[p], acc[r][p]);
                acc[r][p] = fma2(x2, w2[p], acc[r][p]);
                acc[r][p] = fma2(x3, w3[p], acc[r][p]);
            }
        }
    }
}

// ---------------------------------------------------------------------------
// GeneralConv: out[i] = (sum_{j in nbr(i)} h[j]) @ W + 6*b + h[i]
// 1024 blocks x 128 threads; one gathered row per thread.
// ---------------------------------------------------------------------------
__global__ void __launch_bounds__(128, 4) gconv_kernel(
    const float* __restrict__ hin,
    const float* __restrict__ Wc, const float* __restrict__ bc,
    float* __restrict__ out)
{
    extern __shared__ float smf[];
    float* ss = smf;             // 128*64 rot-swizzled gathered sums
    float* Ws = smf + 8192;      // 64*64
    float* bs = smf + 12288;     // 64
    const int tid = threadIdx.x;
    const size_t rowbase = (size_t)blockIdx.x * 128;

    // weights + bias
    float4* Ws4 = (float4*)Ws;
    #pragma unroll
    for (int i = 0; i < 8; i++) Ws4[tid + i*128] = ((const float4*)Wc)[tid + i*128];
    if (tid < 64) bs[tid] = bc[tid];

    // gather-sum: one row per thread, rot-swizzled store
    {
        const int r = tid;
        const int rot = ROTR(r);
        const int* ip = g_idx + (rowbase + r) * KK;
        int nb[6];
        #pragma unroll
        for (int j = 0; j < KK; j++) nb[j] = ip[j];
        #pragma unroll
        for (int half = 0; half < 2; half++) {
            float4 a[8];
            {
                const float4* p = (const float4*)(hin + (size_t)nb[0]*FF) + half*8;
                #pragma unroll
                for (int c = 0; c < 8; c++) a[c] = p[c];
            }
            #pragma unroll
            for (int j = 1; j < KK; j++) {
                const float4* p = (const float4*)(hin + (size_t)nb[j]*FF) + half*8;
                #pragma unroll
                for (int c = 0; c < 8; c++) {
                    float4 v = p[c];
                    a[c].x += v.x; a[c].y += v.y; a[c].z += v.z; a[c].w += v.w;
                }
            }
            #pragma unroll
            for (int c = 0; c < 8; c++) {
                const int col = (half*32 + c*4 + rot) & 63;
                *(float4*)&ss[r*64 + col] = a[c];
            }
        }
    }
    __syncthreads();

    const int rg = tid >> 3, cg8 = (tid & 7) * 8;
    u64 acc[8][4];
    mm88(ss, Ws, acc, rg, cg8);

    #pragma unroll
    for (int r = 0; r < 8; r++) {
        const size_t row = rowbase + rg*8 + r;
        const float4 h0 = *(const float4*)&hin[row*FF + cg8];
        const float4 h1 = *(const float4*)&hin[row*FF + cg8 + 4];
        const float2 p0 = unpack2(acc[r][0]);
        const float2 p1 = unpack2(acc[r][1]);
        const float2 p2 = unpack2(acc[r][2]);
        const float2 p3 = unpack2(acc[r][3]);
        float4 o0, o1;
        o0.x = p0.x + 6.f*bs[cg8+0] + h0.x;
        o0.y = p0.y + 6.f*bs[cg8+1] + h0.y;
        o0.z = p1.x + 6.f*bs[cg8+2] + h0.z;
        o0.w = p1.y + 6.f*bs[cg8+3] + h0.w;
        o1.x = p2.x + 6.f*bs[cg8+4] + h1.x;
        o1.y = p2.y + 6.f*bs[cg8+5] + h1.y;
        o1.z = p3.x + 6.f*bs[cg8+6] + h1.z;
        o1.w = p3.y + 6.f*bs[cg8+7] + h1.w;
        *(float4*)&out[row*FF + cg8]     = o0;
        *(float4*)&out[row*FF + cg8 + 4] = o1;
    }
}

// ---------------------------------------------------------------------------
// Fused prelu(x@W1+b1) -> prelu(.@W2+b2). 1024 blocks x 128 thr.
// ---------------------------------------------------------------------------
__global__ void __launch_bounds__(128, 3) lin12_kernel(
    const float* __restrict__ x,
    const float* __restrict__ W1, const float* __restrict__ b1, const float* __restrict__ a1,
    const float* __restrict__ W2, const float* __restrict__ b2, const float* __restrict__ a2,
    float* __restrict__ out)
{
    extern __shared__ float smf[];
    float* xs = smf;             // 128*64 rot-swizzled activations
    float* Ws = smf + 8192;      // W1 | W2
    float* bs = smf + 16384;     // b1,a1,b2,a2
    const int tid = threadIdx.x;
    const size_t rowbase = (size_t)blockIdx.x * 128;

    float4* Ws4 = (float4*)Ws;
    #pragma unroll
    for (int i = 0; i < 8; i++) {
        Ws4[tid + i*128]        = ((const float4*)W1)[tid + i*128];
        Ws4[1024 + tid + i*128] = ((const float4*)W2)[tid + i*128];
    }
    if (tid < 64) { bs[tid] = b1[tid]; bs[64+tid] = a1[tid]; bs[128+tid] = b2[tid]; bs[192+tid] = a2[tid]; }

    // load x row (rot-swizzled)
    {
        const int r = tid;
        const int rot = ROTR(r);
        const float4* xin = (const float4*)(x + (rowbase + r) * FF);
        #pragma unroll
        for (int c = 0; c < 16; c++) {
            const int col = (c*4 + rot) & 63;
            *(float4*)&xs[r*64 + col] = xin[c];
        }
    }
    __syncthreads();

    const int rg = tid >> 3, cg8 = (tid & 7) * 8;
    const int rot = ROTG(rg);
    u64 acc[8][4];
    mm88(xs, Ws, acc, rg, cg8);
    __syncthreads();
    #pragma unroll
    for (int r = 0; r < 8; r++) {
        const int row = rg*8 + r;
        float4 o0, o1;
        float v;
        const float2 p0 = unpack2(acc[r][0]);
        const float2 p1 = unpack2(acc[r][1]);
        const float2 p2 = unpack2(acc[r][2]);
        const float2 p3 = unpack2(acc[r][3]);
        v = p0.x + bs[cg8+0]; o0.x = (v >= 0.f) ? v : v * bs[64+cg8+0];
        v = p0.y + bs[cg8+1]; o0.y = (v >= 0.f) ? v : v * bs[64+cg8+1];
        v = p1.x + bs[cg8+2]; o0.z = (v >= 0.f) ? v : v * bs[64+cg8+2];
        v = p1.y + bs[cg8+3]; o0.w = (v >= 0.f) ? v : v * bs[64+cg8+3];
        v = p2.x + bs[cg8+4]; o1.x = (v >= 0.f) ? v : v * bs[64+cg8+4];
        v = p2.y + bs[cg8+5]; o1.y = (v >= 0.f) ? v : v * bs[64+cg8+5];
        v = p3.x + bs[cg8+6]; o1.z = (v >= 0.f) ? v : v * bs[64+cg8+6];
        v = p3.y + bs[cg8+7]; o1.w = (v >= 0.f) ? v : v * bs[64+cg8+7];
        *(float4*)&xs[row*64 + ((cg8     + rot) & 63)] = o0;
        *(float4*)&xs[row*64 + ((cg8 + 4 + rot) & 63)] = o1;
    }
    __syncthreads();
    mm88(xs, Ws + 4096, acc, rg, cg8);
    #pragma unroll
    for (int r = 0; r < 8; r++) {
        const size_t row = rowbase + rg*8 + r;
        float4 o0, o1;
        float v;
        const float2 p0 = unpack2(acc[r][0]);
        const float2 p1 = unpack2(acc[r][1]);
        const float2 p2 = unpack2(acc[r][2]);
        const float2 p3 = unpack2(acc[r][3]);
        v = p0.x + bs[128+cg8+0]; o0.x = (v >= 0.f) ? v : v * bs[192+cg8+0];
        v = p0.y + bs[128+cg8+1]; o0.y = (v >= 0.f) ? v : v * bs[192+cg8+1];
        v = p1.x + bs[128+cg8+2]; o0.z = (v >= 0.f) ? v : v * bs[192+cg8+2];
        v = p1.y + bs[128+cg8+3]; o0.w = (v >= 0.f) ? v : v * bs[192+cg8+3];
        v = p2.x + bs[128+cg8+4]; o1.x = (v >= 0.f) ? v : v * bs[192+cg8+4];
        v = p2.y + bs[128+cg8+5]; o1.y = (v >= 0.f) ? v : v * bs[192+cg8+5];
        v = p3.x + bs[128+cg8+6]; o1.z = (v >= 0.f) ? v : v * bs[192+cg8+6];
        v = p3.y + bs[128+cg8+7]; o1.w = (v >= 0.f) ? v : v * bs[192+cg8+7];
        *(float4*)&out[row*FF + cg8]     = o0;
        *(float4*)&out[row*FF + cg8 + 4] = o1;
    }
}

// ---------------------------------------------------------------------------
// Fused prelu(.@W3+b3) -> prelu(.@W4+b4) -> per-block column partials (pool)
// ---------------------------------------------------------------------------
__global__ void __launch_bounds__(128, 3) lin34_pool_kernel(
    const float* __restrict__ hin,
    const float* __restrict__ W3, const float* __restrict__ b3, const float* __restrict__ a3,
    const float* __restrict__ W4, const float* __restrict__ b4, const float* __restrict__ a4)
{
    extern __shared__ float smf[];
    float* xs = smf;             // 128*64 rot-swizzled
    float* Ws = smf + 8192;      // W3 | W4
    float* ps = smf + 16384;     // 16*64 partials
    float* bs = smf + 17408;     // biases
    const int tid = threadIdx.x;
    const size_t rowbase = (size_t)blockIdx.x * 128;

    float4* Ws4 = (float4*)Ws;
    #pragma unroll
    for (int i = 0; i < 8; i++) {
        Ws4[tid + i*128]        = ((const float4*)W3)[tid + i*128];
        Ws4[1024 + tid + i*128] = ((const float4*)W4)[tid + i*128];
    }
    if (tid < 64) { bs[tid] = b3[tid]; bs[64+tid] = a3[tid]; bs[128+tid] = b4[tid]; bs[192+tid] = a4[tid]; }

    {
        const int r = tid;
        const int rot = ROTR(r);
        const float4* xin = (const float4*)(hin + (rowbase + r) * FF);
        #pragma unroll
        for (int c = 0; c < 16; c++) {
            const int col = (c*4 + rot) & 63;
            *(float4*)&xs[r*64 + col] = xin[c];
        }
    }
    __syncthreads();

    const int rg = tid >> 3, cg8 = (tid & 7) * 8;
    const int rot = ROTG(rg);
    u64 acc[8][4];
    mm88(xs, Ws, acc, rg, cg8);
    __syncthreads();
    #pragma unroll
    for (int r = 0; r < 8; r++) {
        const int row = rg*8 + r;
        float4 o0, o1;
        float v;
        const float2 p0 = unpack2(acc[r][0]);
        const float2 p1 = unpack2(acc[r][1]);
        const float2 p2 = unpack2(acc[r][2]);
        const float2 p3 = unpack2(acc[r][3]);
        v = p0.x + bs[cg8+0]; o0.x = (v >= 0.f) ? v : v * bs[64+cg8+0];
        v = p0.y + bs[cg8+1]; o0.y = (v >= 0.f) ? v : v * bs[64+cg8+1];
        v = p1.x + bs[cg8+2]; o0.z = (v >= 0.f) ? v : v * bs[64+cg8+2];
        v = p1.y + bs[cg8+3]; o0.w = (v >= 0.f) ? v : v * bs[64+cg8+3];
        v = p2.x + bs[cg8+4]; o1.x = (v >= 0.f) ? v : v * bs[64+cg8+4];
        v = p2.y + bs[cg8+5]; o1.y = (v >= 0.f) ? v : v * bs[64+cg8+5];
        v = p3.x + bs[cg8+6]; o1.z = (v >= 0.f) ? v : v * bs[64+cg8+6];
        v = p3.y + bs[cg8+7]; o1.w = (v >= 0.f) ? v : v * bs[64+cg8+7];
        *(float4*)&xs[row*64 + ((cg8     + rot) & 63)] = o0;
        *(float4*)&xs[row*64 + ((cg8 + 4 + rot) & 63)] = o1;
    }
    __syncthreads();
    mm88(xs, Ws + 4096, acc, rg, cg8);

    float cs[8] = {0.f,0.f,0.f,0.f,0.f,0.f,0.f,0.f};
    #pragma unroll
    for (int r = 0; r < 8; r++) {
        float v;
        const float2 p0 = unpack2(acc[r][0]);
        const float2 p1 = unpack2(acc[r][1]);
        const float2 p2 = unpack2(acc[r][2]);
        const float2 p3 = unpack2(acc[r][3]);
        v = p0.x + bs[128+cg8+0]; cs[0] += (v >= 0.f) ? v : v * bs[192+cg8+0];
        v = p0.y + bs[128+cg8+1]; cs[1] += (v >= 0.f) ? v : v * bs[192+cg8+1];
        v = p1.x + bs[128+cg8+2]; cs[2] += (v >= 0.f) ? v : v * bs[192+cg8+2];
        v = p1.y + bs[128+cg8+3]; cs[3] += (v >= 0.f) ? v : v * bs[192+cg8+3];
        v = p2.x + bs[128+cg8+4]; cs[4] += (v >= 0.f) ? v : v * bs[192+cg8+4];
        v = p2.y + bs[128+cg8+5]; cs[5] += (v >= 0.f) ? v : v * bs[192+cg8+5];
        v = p3.x + bs[128+cg8+6]; cs[6] += (v >= 0.f) ? v : v * bs[192+cg8+6];
        v = p3.y + bs[128+cg8+7]; cs[7] += (v >= 0.f) ? v : v * bs[192+cg8+7];
    }
    #pragma unroll
    for (int c = 0; c < 8; c++) ps[rg*64 + cg8 + c] = cs[c];
    __syncthreads();

    if (tid < 64) {
        float s = 0.f;
        #pragma unroll
        for (int i = 0; i < 16; i++) s += ps[i*64 + tid];
        g_part[(size_t)blockIdx.x * FF + tid] = s;
    }
}

// ---------------------------------------------------------------------------
// Head MLP: pooled[64] -> 256 -> 256 -> 64 -> 1 (leaky 0.2). One block per graph.
// ---------------------------------------------------------------------------
__global__ void __launch_bounds__(256) head_kernel(
    const float* __restrict__ Wh1, const float* __restrict__ bh1,
    const float* __restrict__ Wh2, const float* __restrict__ bh2,
    const float* __restrict__ Wh3, const float* __restrict__ bh3,
    const float* __restrict__ Wh4, const float* __restrict__ bh4,
    float* __restrict__ out)
{
    __shared__ float p[64], y1[256], y2[256], y3[64];
    const int g = blockIdx.x, t = threadIdx.x;
    if (t < 64) {
        p[t] = g_part[(size_t)(g*4 + 0)*FF + t] + g_part[(size_t)(g*4 + 1)*FF + t]
             + g_part[(size_t)(g*4 + 2)*FF + t] + g_part[(size_t)(g*4 + 3)*FF + t];
    }
    __syncthreads();
    {
        float v = bh1[t];
        #pragma unroll 4
        for (int k = 0; k < 64; k++) v = fmaf(p[k], Wh1[k*256 + t], v);
        y1[t] = (v >= 0.f) ? v : 0.2f * v;
    }
    __syncthreads();
    {
        float v = bh2[t];
        #pragma unroll 4
        for (int k = 0; k < 256; k++) v = fmaf(y1[k], Wh2[k*256 + t], v);
        y2[t] = (v >= 0.f) ? v : 0.2f * v;
    }
    __syncthreads();
    if (t < 64) {
        float v = bh3[t];
        #pragma unroll 4
        for (int k = 0; k < 256; k++) v = fmaf(y2[k], Wh3[k*64 + t], v);
        y3[t] = (v >= 0.f) ? v : 0.2f * v;
    }
    __syncthreads();
    if (t == 0) {
        float v = bh4[0];
        #pragma unroll
        for (int k = 0; k < 64; k++) v = fmaf(y3[k], Wh4[k], v);
        out[g] = v;
    }
}

// ---------------------------------------------------------------------------
extern "C" void kernel_launch(void* const* d_in, const int* in_sizes, int n_in,
                              void* d_out, int out_size)
{
    const float* x   = (const float*)d_in[0];
    const float* W1  = (const float*)d_in[1];
    const float* b1  = (const float*)d_in[2];
    const float* a1  = (const float*)d_in[3];
    const float* W2  = (const float*)d_in[4];
    const float* b2  = (const float*)d_in[5];
    const float* a2  = (const float*)d_in[6];
    const float* Wc1 = (const float*)d_in[7];
    const float* bc1 = (const float*)d_in[8];
    const float* Wc2 = (const float*)d_in[9];
    const float* bc2 = (const float*)d_in[10];
    const float* Wc3 = (const float*)d_in[11];
    const float* bc3 = (const float*)d_in[12];
    const float* Wc4 = (const float*)d_in[13];
    const float* bc4 = (const float*)d_in[14];
    const float* W3  = (const float*)d_in[15];
    const float* b3  = (const float*)d_in[16];
    const float* a3  = (const float*)d_in[17];
    const float* W4  = (const float*)d_in[18];
    const float* b4  = (const float*)d_in[19];
    const float* a4  = (const float*)d_in[20];
    const float* Wh1 = (const float*)d_in[21];
    const float* bh1 = (const float*)d_in[22];
    const float* Wh2 = (const float*)d_in[23];
    const float* bh2 = (const float*)d_in[24];
    const float* Wh3 = (const float*)d_in[25];
    const float* bh3 = (const float*)d_in[26];
    const float* Wh4 = (const float*)d_in[27];
    const float* bh4 = (const float*)d_in[28];
    float* out = (float*)d_out;

    float *hA = nullptr, *hB = nullptr;
    cudaGetSymbolAddress((void**)&hA, g_hA);
    cudaGetSymbolAddress((void**)&hB, g_hB);

    cudaFuncSetAttribute(knn_kernel,       cudaFuncAttributeMaxDynamicSharedMemorySize, KNN_SMEM);
    cudaFuncSetAttribute(lin12_kernel,     cudaFuncAttributeMaxDynamicSharedMemorySize, LIN12_SMEM);
    cudaFuncSetAttribute(gconv_kernel,     cudaFuncAttributeMaxDynamicSharedMemorySize, GCONV_SMEM);
    cudaFuncSetAttribute(lin34_pool_kernel,cudaFuncAttributeMaxDynamicSharedMemorySize, LIN34_SMEM);

    knn_kernel<<<GG, 256, KNN_SMEM>>>(x);
    lin12_kernel<<<TT/128, 128, LIN12_SMEM>>>(x, W1, b1, a1, W2, b2, a2, hA);
    gconv_kernel<<<TT/128, 128, GCONV_SMEM>>>(hA, Wc1, bc1, hB);
    gconv_kernel<<<TT/128, 128, GCONV_SMEM>>>(hB, Wc2, bc2, hA);
    gconv_kernel<<<TT/128, 128, GCONV_SMEM>>>(hA, Wc3, bc3, hB);
    gconv_kernel<<<TT/128, 128, GCONV_SMEM>>>(hB, Wc4, bc4, hA);
    lin34_pool_kernel<<<TT/128, 128, LIN34_SMEM>>>(hA, W3, b3, a3, W4, b4, a4);
    head_kernel<<<GG, 256>>>(Wh1, bh1, Wh2, bh2, Wh3, bh3, Wh4, bh4, out);
}

// round 11
// speedup vs baseline: 1.4902x; 1.0299x over previous
#include <cuda_runtime.h>
#include <cstdint>

#define GG 256
#define NN 512
#define KK 6
#define FF 64

typedef unsigned long long u64;

// ---------------------------------------------------------------------------
// packed f32x2 helpers
// ---------------------------------------------------------------------------
__device__ __forceinline__ u64 fma2(u64 a, u64 b, u64 c) {
    u64 d;
    asm("fma.rn.f32x2 %0, %1, %2, %3;" : "=l"(d) : "l"(a), "l"(b), "l"(c));
    return d;
}
__device__ __forceinline__ u64 pack2(float lo, float hi) {
    u64 d;
    asm("mov.b64 %0, {%1, %2};" : "=l"(d) : "f"(lo), "f"(hi));
    return d;
}
__device__ __forceinline__ float2 unpack2(u64 v) {
    float lo, hi;
    asm("mov.b64 {%0, %1}, %2;" : "=f"(lo), "=f"(hi) : "l"(v));
    return make_float2(lo, hi);
}

// ---------------------------------------------------------------------------
// smem layout (float offsets). Total 56576 floats = 226304 bytes.
//   h    [0 .. 32768)      : node features, float4-rotated: chunk c4 of row r
//                            stored at chunk (c4 + (r&15)) & 15
//   BIG  [32768 .. 49152)  : knn sq | lin W pair (8192f) | gconv s_tile (16384f)
//                            | pool partials / head temps
//   WC   [49152 .. 53248)  : gconv weights (4096f)
//   IDX  [53248 .. 56320)  : knn indices, 512*6 ints
//   BS   [56320 .. 56576)  : biases (b, a pairs)
// ---------------------------------------------------------------------------
#define OF_BIG 32768
#define OF_WC  49152
#define OF_IDX 53248
#define OF_BS  56320
#define SMEM_FLOATS 56576
#define SMEM_BYTES (SMEM_FLOATS * 4)

// ---------------------------------------------------------------------------
// mm over a 256-row tile: 512 threads; rg = tid>>4 (8 rows), cg4 = tid&15
// (float4 column chunk). ROT: x rows read from rotated h; else plain s_tile.
// Accumulation order (k ascending, col-pair FFMA2) identical to the R4 kernel.
// ---------------------------------------------------------------------------
template<bool ROT>
__device__ __forceinline__ void mm256(const float* __restrict__ xs,
                                      const float* __restrict__ Ws,
                                      u64 (&acc)[8][2], int rowbase, int rg, int cg4)
{
    const int cg = cg4 * 4;
    #pragma unroll
    for (int r = 0; r < 8; r++) { acc[r][0] = 0ull; acc[r][1] = 0ull; }
    const int rr0 = (rg & 1) * 8;
    #pragma unroll 2
    for (int kc4 = 0; kc4 < 16; kc4++) {
        const int k0 = kc4 * 4;
        const ulonglong2 w0 = *(const ulonglong2*)&Ws[(k0+0)*64 + cg];
        const ulonglong2 w1 = *(const ulonglong2*)&Ws[(k0+1)*64 + cg];
        const ulonglong2 w2 = *(const ulonglong2*)&Ws[(k0+2)*64 + cg];
        const ulonglong2 w3 = *(const ulonglong2*)&Ws[(k0+3)*64 + cg];
        #pragma unroll
        for (int r = 0; r < 8; r++) {
            const int xi = ROT ? ((kc4 + rr0 + r) & 15) : kc4;
            const float4 xv = *(const float4*)&xs[(rowbase + rg*8 + r)*64 + xi*4];
            const u64 x0 = pack2(xv.x, xv.x);
            const u64 x1 = pack2(xv.y, xv.y);
            const u64 x2 = pack2(xv.z, xv.z);
            const u64 x3 = pack2(xv.w, xv.w);
            acc[r][0] = fma2(x0, w0.x, acc[r][0]);
            acc[r][1] = fma2(x0, w0.y, acc[r][1]);
            acc[r][0] = fma2(x1, w1.x, acc[r][0]);
            acc[r][1] = fma2(x1, w1.y, acc[r][1]);
            acc[r][0] = fma2(x2, w2.x, acc[r][0]);
            acc[r][1] = fma2(x2, w2.y, acc[r][1]);
            acc[r][0] = fma2(x3, w3.x, acc[r][0]);
            acc[r][1] = fma2(x3, w3.y, acc[r][1]);
        }
    }
}

// lin layer: h = prelu(h @ W + b), in place, 2 tiles of 256 rows.
__device__ __forceinline__ void lin_layer(float* __restrict__ sm,
                                          const float* __restrict__ Ws,
                                          const float* __restrict__ BS, int boff,
                                          int rg, int cg4)
{
    float4* h4 = (float4*)sm;
    const int cg = cg4 * 4;
    u64 acc[8][2];
    #pragma unroll 1
    for (int tile = 0; tile < 2; tile++) {
        mm256<true>(sm, Ws, acc, tile * 256, rg, cg4);
        __syncthreads();
        #pragma unroll
        for (int r = 0; r < 8; r++) {
            const int row = tile*256 + rg*8 + r;
            const int rr = (rg*8 + r) & 15;
            const int chunk = (cg4 + rr) & 15;
            const float2 p0 = unpack2(acc[r][0]);
            const float2 p1 = unpack2(acc[r][1]);
            float4 o; float v;
            v = p0.x + BS[boff+cg+0]; o.x = (v >= 0.f) ? v : v * BS[boff+64+cg+0];
            v = p0.y + BS[boff+cg+1]; o.y = (v >= 0.f) ? v : v * BS[boff+64+cg+1];
            v = p1.x + BS[boff+cg+2]; o.z = (v >= 0.f) ? v : v * BS[boff+64+cg+2];
            v = p1.y + BS[boff+cg+3]; o.w = (v >= 0.f) ? v : v * BS[boff+64+cg+3];
            h4[row*16 + chunk] = o;
        }
        __syncthreads();
    }
}

// gather neighbor sums for half H (rows H*256 .. H*256+255) into s_tile (plain)
__device__ __forceinline__ void gather_half(const float* __restrict__ sm,
                                            float* __restrict__ sT,
                                            const int* __restrict__ IDX,
                                            int H, int tid)
{
    const float4* h4 = (const float4*)sm;
    float4* s4 = (float4*)sT;
    const int r_l = tid >> 1;
    const int fh = tid & 1;
    const int row = H*256 + r_l;
    const int* ip = IDX + row * KK;
    float4 a[8];
    {
        const int j = ip[0];
        const int jb = j & 15;
        #pragma unroll
        for (int c = 0; c < 8; c++) {
            const int c4 = fh*8 + c;
            a[c] = h4[j*16 + ((c4 + jb) & 15)];
        }
    }
    #pragma unroll
    for (int n = 1; n < KK; n++) {
        const int j = ip[n];
        const int jb = j & 15;
        #pragma unroll
        for (int c = 0; c < 8; c++) {
            const int c4 = fh*8 + c;
            const float4 v = h4[j*16 + ((c4 + jb) & 15)];
            a[c].x += v.x; a[c].y += v.y; a[c].z += v.z; a[c].w += v.w;
        }
    }
    #pragma unroll
    for (int c = 0; c < 8; c++) s4[r_l*16 + fh*8 + c] = a[c];
}

// gconv epilogue: h[row] = acc + 6*b + h[row] (residual), rows of half H
__device__ __forceinline__ void gconv_write(float* __restrict__ sm,
                                            const float* __restrict__ BS,
                                            u64 (&acc)[8][2], int H, int rg, int cg4)
{
    float4* h4 = (float4*)sm;
    const int cg = cg4 * 4;
    #pragma unroll
    for (int r = 0; r < 8; r++) {
        const int row = H*256 + rg*8 + r;
        const int rr = (rg*8 + r) & 15;
        const int chunk = (cg4 + rr) & 15;
        const float4 hres = h4[row*16 + chunk];
        const float2 p0 = unpack2(acc[r][0]);
        const float2 p1 = unpack2(acc[r][1]);
        float4 o;
        o.x = p0.x + 6.f*BS[cg+0] + hres.x;
        o.y = p0.y + 6.f*BS[cg+1] + hres.y;
        o.z = p1.x + 6.f*BS[cg+2] + hres.z;
        o.w = p1.y + 6.f*BS[cg+3] + hres.w;
        h4[row*16 + chunk] = o;
    }
}

// ===========================================================================
// Mega kernel: whole network, one block per graph, 512 threads.
// ===========================================================================
__global__ void __launch_bounds__(512, 1) mega_kernel(
    const float* __restrict__ x,
    const float* __restrict__ W1, const float* __restrict__ b1, const float* __restrict__ a1,
    const float* __restrict__ W2, const float* __restrict__ b2, const float* __restrict__ a2,
    const float* __restrict__ Wc1, const float* __restrict__ bc1,
    const float* __restrict__ Wc2, const float* __restrict__ bc2,
    const float* __restrict__ Wc3, const float* __restrict__ bc3,
    const float* __restrict__ Wc4, const float* __restrict__ bc4,
    const float* __restrict__ W3, const float* __restrict__ b3, const float* __restrict__ a3,
    const float* __restrict__ W4, const float* __restrict__ b4, const float* __restrict__ a4,
    const float* __restrict__ Wh1, const float* __restrict__ bh1,
    const float* __restrict__ Wh2, const float* __restrict__ bh2,
    const float* __restrict__ Wh3, const float* __restrict__ bh3,
    const float* __restrict__ Wh4, const float* __restrict__ bh4,
    float* __restrict__ out)
{
    extern __shared__ float sm[];
    float4* h4 = (float4*)sm;
    float* BIG = sm + OF_BIG;
    float* WC  = sm + OF_WC;
    int*   IDX = (int*)(sm + OF_IDX);
    float* BS  = sm + OF_BS;

    const int tid = threadIdx.x;
    const int g   = blockIdx.x;
    const int rg  = tid >> 4;
    const int cg4 = tid & 15;
    const float4* xg4 = (const float4*)(x + (size_t)g * NN * FF);

    // ---- load x -> h (rotated) ----
    #pragma unroll
    for (int c = 0, i = tid; c < 16; c++, i += 512) {
        const int row = i >> 4, c4 = i & 15;
        h4[row*16 + ((c4 + (row & 15)) & 15)] = xg4[i];
    }
    __syncthreads();

    // ---- sq (logical chunk order, R4-identical accumulation) ----
    {
        const int row = tid, rr = tid & 15;
        float s = 0.f;
        #pragma unroll
        for (int c4 = 0; c4 < 16; c4++) {
            const float4 v = h4[row*16 + ((c4 + rr) & 15)];
            s += v.x*v.x + v.y*v.y + v.z*v.z + v.w*v.w;
        }
        BIG[row] = s;   // sq lives in BIG during knn
    }
    __syncthreads();

    // ---- kNN: 1 query per thread, FFMA2 dots, strict-< top-6 (R4 replica) ----
    {
        const int q = tid, rq = q & 15;
        u64 xq[32];
        #pragma unroll
        for (int c4 = 0; c4 < 16; c4++) {
            const ulonglong2 v = *(const ulonglong2*)&sm[q*64 + ((c4 + rq) & 15)*4];
            xq[2*c4] = v.x; xq[2*c4+1] = v.y;
        }
        const float sqq = BIG[q];
        float bd[6]; int bi[6];
        #pragma unroll
        for (int t = 0; t < 6; t++) { bd[t] = 3.0e38f; bi[t] = 0; }
        float wv = 3.0e38f; int ws = 0;

        for (int j = 0; j < NN; j++) {
            const int jb = j & 15;
            const float* cjp = sm + j*64;
            u64 a = 0ull, b = 0ull;
            #pragma unroll
            for (int c4 = 0; c4 < 16; c4++) {
                int rc = c4 + jb; rc &= 15;
                const ulonglong2 v = *(const ulonglong2*)&cjp[rc*4];
                a = fma2(xq[2*c4],   v.x, a);
                b = fma2(xq[2*c4+1], v.y, b);
            }
            const float2 fa = unpack2(a), fb = unpack2(b);
            const float dot = (fa.x + fa.y) + (fb.x + fb.y);
            const float d = __fsub_rn(sqq + BIG[j], __fmul_rn(2.f, dot));
            if (j != q && d < wv) {
                bd[ws] = d; bi[ws] = j;
                wv = bd[0]; ws = 0;
                #pragma unroll
                for (int t = 1; t < 6; t++) if (bd[t] > wv) { wv = bd[t]; ws = t; }
            }
        }
        #pragma unroll
        for (int t = 0; t < 6; t++) IDX[q*KK + t] = bi[t];
    }
    __syncthreads();

    // ---- lin1 + lin2 (weights into BIG; sq dead). 1024 float4 per matrix. ----
    {
        #pragma unroll
        for (int c = 0, i = tid; c < 2; c++, i += 512) {
            ((float4*)BIG)[i]        = ((const float4*)W1)[i];
            ((float4*)BIG)[1024 + i] = ((const float4*)W2)[i];
        }
        if (tid < 64) { BS[tid] = b1[tid]; BS[64+tid] = a1[tid]; BS[128+tid] = b2[tid]; BS[192+tid] = a2[tid]; }
        __syncthreads();
        lin_layer(sm, BIG,        BS, 0,   rg, cg4);
        lin_layer(sm, BIG + 4096, BS, 128, rg, cg4);
    }

    // ---- 4 x gconv ----
    const float* Wcs[4] = {Wc1, Wc2, Wc3, Wc4};
    const float* bcs[4] = {bc1, bc2, bc3, bc4};
    #pragma unroll 1
    for (int L = 0; L < 4; L++) {
        #pragma unroll
        for (int c = 0, i = tid; c < 2; c++, i += 512)
            ((float4*)WC)[i] = ((const float4*)Wcs[L])[i];
        if (tid < 64) BS[tid] = bcs[L][tid];
        __syncthreads();

        u64 accA[8][2], accB[8][2];
        gather_half(sm, BIG, IDX, 0, tid);      // s_tile <- sums rows 0..255 (reads old h)
        __syncthreads();
        mm256<false>(BIG, WC, accA, 0, rg, cg4);
        __syncthreads();                        // s reads done before overwrite
        gather_half(sm, BIG, IDX, 1, tid);      // s_tile <- sums rows 256..511 (old h)
        __syncthreads();                        // all h reads done
        gconv_write(sm, BS, accA, 0, rg, cg4);  // overwrite h rows 0..255
        mm256<false>(BIG, WC, accB, 0, rg, cg4);
        gconv_write(sm, BS, accB, 1, rg, cg4);  // overwrite h rows 256..511
        __syncthreads();
    }

    // ---- lin3 + lin4 ----
    {
        #pragma unroll
        for (int c = 0, i = tid; c < 2; c++, i += 512) {
            ((float4*)BIG)[i]        = ((const float4*)W3)[i];
            ((float4*)BIG)[1024 + i] = ((const float4*)W4)[i];
        }
        if (tid < 64) { BS[tid] = b3[tid]; BS[64+tid] = a3[tid]; BS[128+tid] = b4[tid]; BS[192+tid] = a4[tid]; }
        __syncthreads();
        lin_layer(sm, BIG,        BS, 0,   rg, cg4);
        lin_layer(sm, BIG + 4096, BS, 128, rg, cg4);
    }

    // ---- pool: column sums of h over 512 rows (8 segments x 64 rows) ----
    {
        const int c = tid & 63, seg = tid >> 6;
        float s = 0.f;
        #pragma unroll 4
        for (int r2 = 0; r2 < 64; r2++) {
            const int row = seg*64 + r2;
            const int chunk = (((c >> 2) + (row & 15)) & 15);
            s += sm[row*64 + chunk*4 + (c & 3)];
        }
        BIG[1024 + seg*64 + c] = s;
    }
    __syncthreads();
    if (tid < 64) {
        float ps = 0.f;
        #pragma unroll
        for (int seg = 0; seg < 8; seg++) ps += BIG[1024 + seg*64 + tid];
        BIG[1536 + tid] = ps;     // pooled[64]
    }
    __syncthreads();

    // ---- head MLP: 64 -> 256 -> 256 -> 64 -> 1 (leaky 0.2) ----
    {
        float* pooled = BIG + 1536;
        float* y1 = BIG;          // [0..256)
        float* y2 = BIG + 256;    // [256..512)
        float* y3 = BIG + 512;    // [512..576)
        if (tid < 256) {
            float v = bh1[tid];
            #pragma unroll 4
            for (int k = 0; k < 64; k++) v = fmaf(pooled[k], Wh1[k*256 + tid], v);
            y1[tid] = (v >= 0.f) ? v : 0.2f * v;
        }
        __syncthreads();
        if (tid < 256) {
            float v = bh2[tid];
            #pragma unroll 4
            for (int k = 0; k < 256; k++) v = fmaf(y1[k], Wh2[k*256 + tid], v);
            y2[tid] = (v >= 0.f) ? v : 0.2f * v;
        }
        __syncthreads();
        if (tid < 64) {
            float v = bh3[tid];
            #pragma unroll 4
            for (int k = 0; k < 256; k++) v = fmaf(y2[k], Wh3[k*64 + tid], v);
            y3[tid] = (v >= 0.f) ? v : 0.2f * v;
        }
        __syncthreads();
        if (tid == 0) {
            float v = bh4[0];
            #pragma unroll
            for (int k = 0; k < 64; k++) v = fmaf(y3[k], Wh4[k], v);
            out[g] = v;
        }
    }
}

// ---------------------------------------------------------------------------
extern "C" void kernel_launch(void* const* d_in, const int* in_sizes, int n_in,
                              void* d_out, int out_size)
{
    const float* x   = (const float*)d_in[0];
    const float* W1  = (const float*)d_in[1];
    const float* b1  = (const float*)d_in[2];
    const float* a1  = (const float*)d_in[3];
    const float* W2  = (const float*)d_in[4];
    const float* b2  = (const float*)d_in[5];
    const float* a2  = (const float*)d_in[6];
    const float* Wc1 = (const float*)d_in[7];
    const float* bc1 = (const float*)d_in[8];
    const float* Wc2 = (const float*)d_in[9];
    const float* bc2 = (const float*)d_in[10];
    const float* Wc3 = (const float*)d_in[11];
    const float* bc3 = (const float*)d_in[12];
    const float* Wc4 = (const float*)d_in[13];
    const float* bc4 = (const float*)d_in[14];
    const float* W3  = (const float*)d_in[15];
    const float* b3  = (const float*)d_in[16];
    const float* a3  = (const float*)d_in[17];
    const float* W4  = (const float*)d_in[18];
    const float* b4  = (const float*)d_in[19];
    const float* a4  = (const float*)d_in[20];
    const float* Wh1 = (const float*)d_in[21];
    const float* bh1 = (const float*)d_in[22];
    const float* Wh2 = (const float*)d_in[23];
    const float* bh2 = (const float*)d_in[24];
    const float* Wh3 = (const float*)d_in[25];
    const float* bh3 = (const float*)d_in[26];
    const float* Wh4 = (const float*)d_in[27];
    const float* bh4 = (const float*)d_in[28];
    float* out = (float*)d_out;

    cudaFuncSetAttribute(mega_kernel, cudaFuncAttributeMaxDynamicSharedMemorySize, SMEM_BYTES);
    mega_kernel<<<GG, 512, SMEM_BYTES>>>(
        x, W1, b1, a1, W2, b2, a2,
        Wc1, bc1, Wc2, bc2, Wc3, bc3, Wc4, bc4,
        W3, b3, a3, W4, b4, a4,
        Wh1, bh1, Wh2, bh2, Wh3, bh3, Wh4, bh4, out);
}

// round 12
// speedup vs baseline: 1.7400x; 1.1676x over previous
#include <cuda_runtime.h>
#include <cstdint>

#define GG 256
#define NN 512
#define KK 6
#define FF 64
#define PADH 68          // floats per h row (272B, 16B-aligned, bank shift 4)

typedef unsigned long long u64;
typedef unsigned short u16;

// ---------------------------------------------------------------------------
// packed f32x2 helpers
// ---------------------------------------------------------------------------
__device__ __forceinline__ u64 fma2(u64 a, u64 b, u64 c) {
    u64 d;
    asm("fma.rn.f32x2 %0, %1, %2, %3;" : "=l"(d) : "l"(a), "l"(b), "l"(c));
    return d;
}
__device__ __forceinline__ u64 pack2(float lo, float hi) {
    u64 d;
    asm("mov.b64 %0, {%1, %2};" : "=l"(d) : "f"(lo), "f"(hi));
    return d;
}
__device__ __forceinline__ float2 unpack2(u64 v) {
    float lo, hi;
    asm("mov.b64 {%0, %1}, %2;" : "=f"(lo), "=f"(hi) : "l"(v));
    return make_float2(lo, hi);
}

// ---------------------------------------------------------------------------
// smem layout (float offsets). Total 57088 floats = 228352 bytes (<= 232448).
//   h    [0 .. 34816)        : node features, plain, PADH=68 floats/row
//   BIG  [34816 .. 51200)    : knn sq | lin W pair (8192f) | gconv s_tile 256x64
//                              | pool partials / head temps
//   WC   [51200 .. 55296)    : gconv weights (4096f)
//   IDX  [55296 .. 56832)    : knn indices, 512*6 u16 (3072 shorts)
//   BS   [56832 .. 57088)    : biases (b, a pairs)
// ---------------------------------------------------------------------------
#define OF_BIG 34816
#define OF_WC  51200
#define OF_IDX 55296
#define OF_BS  56832
#define SMEM_FLOATS 57088
#define SMEM_BYTES (SMEM_FLOATS * 4)

// ---------------------------------------------------------------------------
// mm over a 256-row tile: 512 threads; rg = tid>>4 (8 rows), cg4 = tid&15.
// xs has PAD floats per row (68 for h, 64 for s_tile). Plain k-ascending order
// (identical accumulation to R4/R11).
// ---------------------------------------------------------------------------
template<int PAD>
__device__ __forceinline__ void mm256(const float* __restrict__ xs,
                                      const float* __restrict__ Ws,
                                      u64 (&acc)[8][2], int rowbase, int rg, int cg4)
{
    const int cg = cg4 * 4;
    #pragma unroll
    for (int r = 0; r < 8; r++) { acc[r][0] = 0ull; acc[r][1] = 0ull; }
    #pragma unroll 2
    for (int kc4 = 0; kc4 < 16; kc4++) {
        const int k0 = kc4 * 4;
        const ulonglong2 w0 = *(const ulonglong2*)&Ws[(k0+0)*64 + cg];
        const ulonglong2 w1 = *(const ulonglong2*)&Ws[(k0+1)*64 + cg];
        const ulonglong2 w2 = *(const ulonglong2*)&Ws[(k0+2)*64 + cg];
        const ulonglong2 w3 = *(const ulonglong2*)&Ws[(k0+3)*64 + cg];
        #pragma unroll
        for (int r = 0; r < 8; r++) {
            const float4 xv = *(const float4*)&xs[(rowbase + rg*8 + r)*PAD + k0];
            const u64 x0 = pack2(xv.x, xv.x);
            const u64 x1 = pack2(xv.y, xv.y);
            const u64 x2 = pack2(xv.z, xv.z);
            const u64 x3 = pack2(xv.w, xv.w);
            acc[r][0] = fma2(x0, w0.x, acc[r][0]);
            acc[r][1] = fma2(x0, w0.y, acc[r][1]);
            acc[r][0] = fma2(x1, w1.x, acc[r][0]);
            acc[r][1] = fma2(x1, w1.y, acc[r][1]);
            acc[r][0] = fma2(x2, w2.x, acc[r][0]);
            acc[r][1] = fma2(x2, w2.y, acc[r][1]);
            acc[r][0] = fma2(x3, w3.x, acc[r][0]);
            acc[r][1] = fma2(x3, w3.y, acc[r][1]);
        }
    }
}

// lin layer: h = prelu(h @ W + b), in place, 2 tiles of 256 rows.
__device__ __forceinline__ void lin_layer(float* __restrict__ sm,
                                          const float* __restrict__ Ws,
                                          const float* __restrict__ BS, int boff,
                                          int rg, int cg4)
{
    float4* h4 = (float4*)sm;
    const int cg = cg4 * 4;
    u64 acc[8][2];
    #pragma unroll 1
    for (int tile = 0; tile < 2; tile++) {
        mm256<PADH>(sm, Ws, acc, tile * 256, rg, cg4);
        __syncthreads();
        #pragma unroll
        for (int r = 0; r < 8; r++) {
            const int row = tile*256 + rg*8 + r;
            const float2 p0 = unpack2(acc[r][0]);
            const float2 p1 = unpack2(acc[r][1]);
            float4 o; float v;
            v = p0.x + BS[boff+cg+0]; o.x = (v >= 0.f) ? v : v * BS[boff+64+cg+0];
            v = p0.y + BS[boff+cg+1]; o.y = (v >= 0.f) ? v : v * BS[boff+64+cg+1];
            v = p1.x + BS[boff+cg+2]; o.z = (v >= 0.f) ? v : v * BS[boff+64+cg+2];
            v = p1.y + BS[boff+cg+3]; o.w = (v >= 0.f) ? v : v * BS[boff+64+cg+3];
            h4[row*17 + cg4] = o;
        }
        __syncthreads();
    }
}

// gather neighbor sums for half H (rows H*256 .. H*256+255) into s_tile (64/row)
__device__ __forceinline__ void gather_half(const float* __restrict__ sm,
                                            float* __restrict__ sT,
                                            const u16* __restrict__ IDX,
                                            int H, int tid)
{
    const float4* h4 = (const float4*)sm;
    float4* s4 = (float4*)sT;
    const int r_l = tid >> 1;
    const int fh = tid & 1;
    const int row = H*256 + r_l;
    const u16* ip = IDX + row * KK;
    float4 a[8];
    {
        const int j = ip[0];
        #pragma unroll
        for (int c = 0; c < 8; c++) a[c] = h4[j*17 + fh*8 + c];
    }
    #pragma unroll
    for (int n = 1; n < KK; n++) {
        const int j = ip[n];
        #pragma unroll
        for (int c = 0; c < 8; c++) {
            const float4 v = h4[j*17 + fh*8 + c];
            a[c].x += v.x; a[c].y += v.y; a[c].z += v.z; a[c].w += v.w;
        }
    }
    #pragma unroll
    for (int c = 0; c < 8; c++) s4[r_l*16 + fh*8 + c] = a[c];
}

// gconv epilogue: h[row] = acc + 6*b + h[row] (residual), rows of half H
__device__ __forceinline__ void gconv_write(float* __restrict__ sm,
                                            const float* __restrict__ BS,
                                            u64 (&acc)[8][2], int H, int rg, int cg4)
{
    float4* h4 = (float4*)sm;
    const int cg = cg4 * 4;
    #pragma unroll
    for (int r = 0; r < 8; r++) {
        const int row = H*256 + rg*8 + r;
        const float4 hres = h4[row*17 + cg4];
        const float2 p0 = unpack2(acc[r][0]);
        const float2 p1 = unpack2(acc[r][1]);
        float4 o;
        o.x = p0.x + 6.f*BS[cg+0] + hres.x;
        o.y = p0.y + 6.f*BS[cg+1] + hres.y;
        o.z = p1.x + 6.f*BS[cg+2] + hres.z;
        o.w = p1.y + 6.f*BS[cg+3] + hres.w;
        h4[row*17 + cg4] = o;
    }
}

// ===========================================================================
// Mega kernel: whole network, one block per graph, 512 threads.
// ===========================================================================
__global__ void __launch_bounds__(512, 1) mega_kernel(
    const float* __restrict__ x,
    const float* __restrict__ W1, const float* __restrict__ b1, const float* __restrict__ a1,
    const float* __restrict__ W2, const float* __restrict__ b2, const float* __restrict__ a2,
    const float* __restrict__ Wc1, const float* __restrict__ bc1,
    const float* __restrict__ Wc2, const float* __restrict__ bc2,
    const float* __restrict__ Wc3, const float* __restrict__ bc3,
    const float* __restrict__ Wc4, const float* __restrict__ bc4,
    const float* __restrict__ W3, const float* __restrict__ b3, const float* __restrict__ a3,
    const float* __restrict__ W4, const float* __restrict__ b4, const float* __restrict__ a4,
    const float* __restrict__ Wh1, const float* __restrict__ bh1,
    const float* __restrict__ Wh2, const float* __restrict__ bh2,
    const float* __restrict__ Wh3, const float* __restrict__ bh3,
    const float* __restrict__ Wh4, const float* __restrict__ bh4,
    float* __restrict__ out)
{
    extern __shared__ float sm[];
    float4* h4 = (float4*)sm;
    float* BIG = sm + OF_BIG;
    float* WC  = sm + OF_WC;
    u16*   IDX = (u16*)(sm + OF_IDX);
    float* BS  = sm + OF_BS;

    const int tid = threadIdx.x;
    const int g   = blockIdx.x;
    const int rg  = tid >> 4;
    const int cg4 = tid & 15;
    const float4* xg4 = (const float4*)(x + (size_t)g * NN * FF);

    // ---- load x -> h (plain, padded) ----
    #pragma unroll
    for (int c = 0, i = tid; c < 16; c++, i += 512) {
        const int row = i >> 4, c4 = i & 15;
        h4[row*17 + c4] = xg4[i];
    }
    __syncthreads();

    // ---- sq (k-ascending, R4-identical accumulation) ----
    {
        const int row = tid;
        float s = 0.f;
        #pragma unroll
        for (int c4 = 0; c4 < 16; c4++) {
            const float4 v = h4[row*17 + c4];
            s += v.x*v.x + v.y*v.y + v.z*v.z + v.w*v.w;
        }
        BIG[row] = s;   // sq lives in BIG during knn
    }
    __syncthreads();

    // ---- kNN: 1 query per thread, FFMA2 dots (4 chains), strict-< top-6 ----
    {
        const int q = tid;
        u64 xq[32];
        #pragma unroll
        for (int c4 = 0; c4 < 16; c4++) {
            const ulonglong2 v = *(const ulonglong2*)&sm[q*PADH + c4*4];
            xq[2*c4] = v.x; xq[2*c4+1] = v.y;
        }
        const float sqq = BIG[q];
        float bd[6]; int bi[6];
        #pragma unroll
        for (int t = 0; t < 6; t++) { bd[t] = 3.0e38f; bi[t] = 0; }
        float wv = 3.0e38f; int ws = 0;

        const float* cjp = sm;
        for (int j = 0; j < NN; j++, cjp += PADH) {
            u64 a = 0ull, b = 0ull, cch = 0ull, dch = 0ull;
            #pragma unroll
            for (int c4 = 0; c4 < 16; c4 += 2) {
                const ulonglong2 v0 = *(const ulonglong2*)&cjp[c4*4];
                const ulonglong2 v1 = *(const ulonglong2*)&cjp[c4*4 + 4];
                a   = fma2(xq[2*c4],   v0.x, a);
                b   = fma2(xq[2*c4+1], v0.y, b);
                cch = fma2(xq[2*c4+2], v1.x, cch);
                dch = fma2(xq[2*c4+3], v1.y, dch);
            }
            const float2 fa = unpack2(a), fb = unpack2(b);
            const float2 fc = unpack2(cch), fd = unpack2(dch);
            const float dot = ((fa.x + fa.y) + (fb.x + fb.y))
                            + ((fc.x + fc.y) + (fd.x + fd.y));
            const float d = __fsub_rn(sqq + BIG[j], __fmul_rn(2.f, dot));
            if (j != q && d < wv) {
                bd[ws] = d; bi[ws] = j;
                wv = bd[0]; ws = 0;
                #pragma unroll
                for (int t = 1; t < 6; t++) if (bd[t] > wv) { wv = bd[t]; ws = t; }
            }
        }
        #pragma unroll
        for (int t = 0; t < 6; t++) IDX[q*KK + t] = (u16)bi[t];
    }
    __syncthreads();

    // ---- lin1 + lin2 (weights into BIG; sq dead). 1024 float4 per matrix. ----
    {
        #pragma unroll
        for (int c = 0, i = tid; c < 2; c++, i += 512) {
            ((float4*)BIG)[i]        = ((const float4*)W1)[i];
            ((float4*)BIG)[1024 + i] = ((const float4*)W2)[i];
        }
        if (tid < 64) { BS[tid] = b1[tid]; BS[64+tid] = a1[tid]; BS[128+tid] = b2[tid]; BS[192+tid] = a2[tid]; }
        __syncthreads();
        lin_layer(sm, BIG,        BS, 0,   rg, cg4);
        lin_layer(sm, BIG + 4096, BS, 128, rg, cg4);
    }

    // ---- 4 x gconv ----
    const float* Wcs[4] = {Wc1, Wc2, Wc3, Wc4};
    const float* bcs[4] = {bc1, bc2, bc3, bc4};
    #pragma unroll 1
    for (int L = 0; L < 4; L++) {
        #pragma unroll
        for (int c = 0, i = tid; c < 2; c++, i += 512)
            ((float4*)WC)[i] = ((const float4*)Wcs[L])[i];
        if (tid < 64) BS[tid] = bcs[L][tid];
        __syncthreads();

        u64 accA[8][2], accB[8][2];
        gather_half(sm, BIG, IDX, 0, tid);      // s_tile <- sums rows 0..255 (reads old h)
        __syncthreads();
        mm256<64>(BIG, WC, accA, 0, rg, cg4);
        __syncthreads();                        // s reads done before overwrite
        gather_half(sm, BIG, IDX, 1, tid);      // s_tile <- sums rows 256..511 (old h)
        __syncthreads();                        // all h reads done
        gconv_write(sm, BS, accA, 0, rg, cg4);  // overwrite h rows 0..255
        mm256<64>(BIG, WC, accB, 0, rg, cg4);
        gconv_write(sm, BS, accB, 1, rg, cg4);  // overwrite h rows 256..511
        __syncthreads();
    }

    // ---- lin3 + lin4 ----
    {
        #pragma unroll
        for (int c = 0, i = tid; c < 2; c++, i += 512) {
            ((float4*)BIG)[i]        = ((const float4*)W3)[i];
            ((float4*)BIG)[1024 + i] = ((const float4*)W4)[i];
        }
        if (tid < 64) { BS[tid] = b3[tid]; BS[64+tid] = a3[tid]; BS[128+tid] = b4[tid]; BS[192+tid] = a4[tid]; }
        __syncthreads();
        lin_layer(sm, BIG,        BS, 0,   rg, cg4);
        lin_layer(sm, BIG + 4096, BS, 128, rg, cg4);
    }

    // ---- pool: column sums of h over 512 rows (8 segments x 64 rows) ----
    {
        const int c = tid & 63, seg = tid >> 6;
        float s = 0.f;
        #pragma unroll 4
        for (int r2 = 0; r2 < 64; r2++) {
            const int row = seg*64 + r2;
            s += sm[row*PADH + c];
        }
        BIG[1024 + seg*64 + c] = s;
    }
    __syncthreads();
    if (tid < 64) {
        float ps = 0.f;
        #pragma unroll
        for (int seg = 0; seg < 8; seg++) ps += BIG[1024 + seg*64 + tid];
        BIG[1536 + tid] = ps;     // pooled[64]
    }
    __syncthreads();

    // ---- head MLP: 64 -> 256 -> 256 -> 64 -> 1 (leaky 0.2) ----
    {
        float* pooled = BIG + 1536;
        float* y1 = BIG;          // [0..256)
        float* y2 = BIG + 256;    // [256..512)
        float* y3 = BIG + 512;    // [512..576)
        if (tid < 256) {
            float v = bh1[tid];
            #pragma unroll 4
            for (int k = 0; k < 64; k++) v = fmaf(pooled[k], Wh1[k*256 + tid], v);
            y1[tid] = (v >= 0.f) ? v : 0.2f * v;
        }
        __syncthreads();
        if (tid < 256) {
            float v = bh2[tid];
            #pragma unroll 4
            for (int k = 0; k < 256; k++) v = fmaf(y1[k], Wh2[k*256 + tid], v);
            y2[tid] = (v >= 0.f) ? v : 0.2f * v;
        }
        __syncthreads();
        if (tid < 64) {
            float v = bh3[tid];
            #pragma unroll 4
            for (int k = 0; k < 256; k++) v = fmaf(y2[k], Wh3[k*64 + tid], v);
            y3[tid] = (v >= 0.f) ? v : 0.2f * v;
        }
        __syncthreads();
        if (tid == 0) {
            float v = bh4[0];
            #pragma unroll
            for (int k = 0; k < 64; k++) v = fmaf(y3[k], Wh4[k], v);
            out[g] = v;
        }
    }
}

// ---------------------------------------------------------------------------
extern "C" void kernel_launch(void* const* d_in, const int* in_sizes, int n_in,
                              void* d_out, int out_size)
{
    const float* x   = (const float*)d_in[0];
    const float* W1  = (const float*)d_in[1];
    const float* b1  = (const float*)d_in[2];
    const float* a1  = (const float*)d_in[3];
    const float* W2  = (const float*)d_in[4];
    const float* b2  = (const float*)d_in[5];
    const float* a2  = (const float*)d_in[6];
    const float* Wc1 = (const float*)d_in[7];
    const float* bc1 = (const float*)d_in[8];
    const float* Wc2 = (const float*)d_in[9];
    const float* bc2 = (const float*)d_in[10];
    const float* Wc3 = (const float*)d_in[11];
    const float* bc3 = (const float*)d_in[12];
    const float* Wc4 = (const float*)d_in[13];
    const float* bc4 = (const float*)d_in[14];
    const float* W3  = (const float*)d_in[15];
    const float* b3  = (const float*)d_in[16];
    const float* a3  = (const float*)d_in[17];
    const float* W4  = (const float*)d_in[18];
    const float* b4  = (const float*)d_in[19];
    const float* a4  = (const float*)d_in[20];
    const float* Wh1 = (const float*)d_in[21];
    const float* bh1 = (const float*)d_in[22];
    const float* Wh2 = (const float*)d_in[23];
    const float* bh2 = (const float*)d_in[24];
    const float* Wh3 = (const float*)d_in[25];
    const float* bh3 = (const float*)d_in[26];
    const float* Wh4 = (const float*)d_in[27];
    const float* bh4 = (const float*)d_in[28];
    float* out = (float*)d_out;

    cudaFuncSetAttribute(mega_kernel, cudaFuncAttributeMaxDynamicSharedMemorySize, SMEM_BYTES);
    mega_kernel<<<GG, 512, SMEM_BYTES>>>(
        x, W1, b1, a1, W2, b2, a2,
        Wc1, bc1, Wc2, bc2, Wc3, bc3, Wc4, bc4,
        W3, b3, a3, W4, b4, a4,
        Wh1, bh1, Wh2, bh2, Wh3, bh3, Wh4, bh4, out);
}